// round 7
// baseline (speedup 1.0000x reference)
#include <cuda_runtime.h>

// SharedSharedLoss: mean off-diagonal pairwise squared L2 distance / C.
// Identity: sum_{i,j} ||a_i - a_j||^2 = 2N * S2 - 2 * ||colsum||^2
//
// Column-complete decomposition: 64 blocks, each owns an 8-column strip over
// ALL 4096 rows => every block computes its FINAL contribution to ||colsum||^2
// and S2 internally. Cross-block state is one double2 per block (1 KB), and
// the last-block tail is a single-warp reduce. One launch.

#define N_ROWS 4096
#define N_COLS 512
#define N_COLS4 128                  // float4 groups per row
#define GRID 64                      // one 8-col strip (2 float4 groups) each
#define BLK 512                      // 2 groups x 256 row-lanes
#define ROW_LANES 256
#define LPT (N_ROWS / ROW_LANES)     // 16 loads per thread (2 batches of 8)
#define NWARPS (BLK / 32)            // 16

// Deterministic scratch (no float atomics anywhere).
__device__ double2 g_part[GRID];         // per-block (dnrm, s2) — final doubles
__device__ unsigned int g_count = 0;     // completion counter (reset by last block)

__global__ __launch_bounds__(BLK, 1) void fused_kernel(const float* __restrict__ A,
                                                       float* __restrict__ out) {
    const int t  = threadIdx.x;
    const int g  = t & 1;            // float4 group within strip (0..1)
    const int r0 = t >> 1;           // row lane (0..255)
    const int b  = blockIdx.x;       // column strip: cols [b*8, b*8+8)

    const float4* __restrict__ A4 = reinterpret_cast<const float4*>(A);

    // ---- Streaming: 4096 rows x 8 cols per block, 16 loads (2x8 batches) ----
    const int base = r0 * N_COLS4 + b * 2 + g;
    float4 c = make_float4(0.f, 0.f, 0.f, 0.f);
    float s2 = 0.f;

    #pragma unroll
    for (int batch = 0; batch < 2; batch++) {
        float4 v[8];
        #pragma unroll
        for (int i = 0; i < 8; i++)
            v[i] = A4[base + (batch * 8 + i) * ROW_LANES * N_COLS4];
        #pragma unroll
        for (int i = 0; i < 8; i++) {
            c.x += v[i].x; c.y += v[i].y; c.z += v[i].z; c.w += v[i].w;
            s2 += v[i].x * v[i].x + v[i].y * v[i].y
                + v[i].z * v[i].z + v[i].w * v[i].w;
        }
    }

    // ---- Warp reduce: lanes with same g differ by 2,4,8,16 in lane id ----
    #pragma unroll
    for (int off = 16; off >= 2; off >>= 1) {
        c.x += __shfl_down_sync(0xFFFFFFFFu, c.x, off);
        c.y += __shfl_down_sync(0xFFFFFFFFu, c.y, off);
        c.z += __shfl_down_sync(0xFFFFFFFFu, c.z, off);
        c.w += __shfl_down_sync(0xFFFFFFFFu, c.w, off);
    }
    #pragma unroll
    for (int off = 16; off > 0; off >>= 1)
        s2 += __shfl_down_sync(0xFFFFFFFFu, s2, off);

    __shared__ float4 sh[NWARPS * 2];        // [warp][group]
    __shared__ float  warp_s2[NWARPS];
    const int w = t >> 5, lane = t & 31;
    if (lane < 2) sh[w * 2 + lane] = c;      // lane == g for lanes 0..1
    if (lane == 0) warp_s2[w] = s2;
    __syncthreads();

    // ---- Block combine: complete colsums -> final double contribution ----
    if (t == 0) {
        float4 g0 = make_float4(0.f, 0.f, 0.f, 0.f);
        float4 g1 = make_float4(0.f, 0.f, 0.f, 0.f);
        float s2t = 0.f;
        #pragma unroll
        for (int k = 0; k < NWARPS; k++) {
            float4 a = sh[k * 2 + 0], d = sh[k * 2 + 1];
            g0.x += a.x; g0.y += a.y; g0.z += a.z; g0.w += a.w;
            g1.x += d.x; g1.y += d.y; g1.z += d.z; g1.w += d.w;
            s2t += warp_s2[k];
        }
        double dnrm = (double)g0.x * g0.x + (double)g0.y * g0.y
                    + (double)g0.z * g0.z + (double)g0.w * g0.w
                    + (double)g1.x * g1.x + (double)g1.y * g1.y
                    + (double)g1.z * g1.z + (double)g1.w * g1.w;
        g_part[b] = make_double2(dnrm, (double)s2t);
    }

    // ---- Last-block-done tail (single warp) ----
    __threadfence();
    __syncthreads();
    __shared__ bool isLast;
    if (t == 0)
        isLast = (atomicAdd(&g_count, 1u) == GRID - 1);
    __syncthreads();
    if (!isLast || t >= 64) return;

    double2 p = g_part[t];           // 64 threads, 1 KB, L2-resident
    double dnrm = p.x, ds2 = p.y;
    // Reduce across 2 warps via shuffles + 1 smem handoff.
    #pragma unroll
    for (int off = 16; off > 0; off >>= 1) {
        dnrm += __shfl_down_sync(0xFFFFFFFFu, dnrm, off);
        ds2  += __shfl_down_sync(0xFFFFFFFFu, ds2, off);
    }
    __shared__ double fin[4];
    if (lane == 0) { fin[w * 2] = dnrm; fin[w * 2 + 1] = ds2; }
    __syncthreads();
    if (t == 0) {
        double NS = fin[0] + fin[2];
        double S2 = fin[1] + fin[3];
        const double N = (double)N_ROWS;
        const double C = (double)N_COLS;
        double total = (2.0 * N * S2 - 2.0 * NS) / C;
        out[0] = (float)(total / (N * (N - 1.0)));
        g_count = 0;   // reset for next graph replay
    }
}

extern "C" void kernel_launch(void* const* d_in, const int* in_sizes, int n_in,
                              void* d_out, int out_size) {
    const float* A = (const float*)d_in[0];
    float* out = (float*)d_out;
    (void)in_sizes; (void)n_in; (void)out_size;

    fused_kernel<<<GRID, BLK>>>(A, out);
}

// round 8
// speedup vs baseline: 1.1158x; 1.1158x over previous
#include <cuda_runtime.h>

// SharedSharedLoss: mean off-diagonal pairwise squared L2 distance / C.
// Identity: sum_{i,j} ||a_i - a_j||^2 = 2N * S2 - 2 * ||colsum||^2
//
// pass1: 16 col-strips x 8 row-chunks = 128 blocks x 512 thr; 8 independent
//        float4 loads/thread; shuffle + one-barrier reduce; 16 KB partials;
//        threadfence + cudaTriggerProgrammaticLaunchCompletion.
// pass2: launched with PDL (programmatic stream serialization) so it overlaps
//        pass1; cudaGridDependencySynchronize() then tiny L2 reduce + combine.
// No atomics anywhere -> bit-deterministic across replays.

#define N_ROWS 4096
#define N_COLS 512
#define N_COLS4 128                  // float4 groups per row
#define N_STRIPS 16                  // column strips of 32 cols (8 float4 groups)
#define N_CHUNKS 8                   // row chunks of 512 rows
#define GRID1 (N_STRIPS * N_CHUNKS)  // 128 blocks
#define BLK 512                      // 8 col-groups x 64 row-lanes
#define ROWS_PER_CHUNK (N_ROWS / N_CHUNKS)   // 512
#define ROW_LANES 64
#define LPT (ROWS_PER_CHUNK / ROW_LANES)     // 8 loads per thread
#define NWARPS (BLK / 32)                    // 16

__device__ float g_colpart[GRID1 * 32];   // [rc*16+cs][32 cols] = 16 KB
__device__ float g_s2part[GRID1];

__global__ __launch_bounds__(BLK, 1) void pass1_kernel(const float* __restrict__ A) {
    const int t  = threadIdx.x;
    const int g  = t & 7;            // float4 group within strip (0..7)
    const int r0 = t >> 3;           // row lane (0..63)
    const int b  = blockIdx.x;
    const int cs = b & (N_STRIPS - 1);   // column strip
    const int rc = b >> 4;               // row chunk

    const float4* __restrict__ A4 = reinterpret_cast<const float4*>(A);

    // ---- Streaming: 512 rows x 32 cols per block, 8 independent loads ----
    const int base = (rc * ROWS_PER_CHUNK + r0) * N_COLS4 + cs * 8 + g;
    float4 v[LPT];
    #pragma unroll
    for (int i = 0; i < LPT; i++)
        v[i] = A4[base + i * ROW_LANES * N_COLS4];

    float4 c = make_float4(0.f, 0.f, 0.f, 0.f);
    float s2 = 0.f;
    #pragma unroll
    for (int i = 0; i < LPT; i++) {
        c.x += v[i].x; c.y += v[i].y; c.z += v[i].z; c.w += v[i].w;
        s2 += v[i].x * v[i].x + v[i].y * v[i].y
            + v[i].z * v[i].z + v[i].w * v[i].w;
    }

    // ---- Warp reduce (lanes with same g differ by 8 in lane id) ----
    #pragma unroll
    for (int off = 16; off >= 8; off >>= 1) {
        c.x += __shfl_down_sync(0xFFFFFFFFu, c.x, off);
        c.y += __shfl_down_sync(0xFFFFFFFFu, c.y, off);
        c.z += __shfl_down_sync(0xFFFFFFFFu, c.z, off);
        c.w += __shfl_down_sync(0xFFFFFFFFu, c.w, off);
    }
    #pragma unroll
    for (int off = 16; off > 0; off >>= 1)
        s2 += __shfl_down_sync(0xFFFFFFFFu, s2, off);

    __shared__ float4 sh[NWARPS * 8];       // [warp][group]
    __shared__ float  warp_s2[NWARPS];
    const int w = t >> 5, lane = t & 31;
    if (lane < 8) sh[w * 8 + lane] = c;     // lane == g for lanes 0..7
    if (lane == 0) warp_s2[w] = s2;
    __syncthreads();

    // ---- Final combine (flat 16-way sums) + partial store ----
    if (t < 8) {
        float4 acc = make_float4(0.f, 0.f, 0.f, 0.f);
        #pragma unroll
        for (int k = 0; k < NWARPS; k++) {
            float4 m = sh[k * 8 + t];
            acc.x += m.x; acc.y += m.y; acc.z += m.z; acc.w += m.w;
        }
        reinterpret_cast<float4*>(g_colpart)[b * 8 + t] = acc;
    } else if (t == 8) {
        float tot = 0.f;
        #pragma unroll
        for (int k = 0; k < NWARPS; k++) tot += warp_s2[k];
        g_s2part[b] = tot;
    }

    // Make partials visible, then release the dependent (PDL) kernel.
    __threadfence();
    cudaTriggerProgrammaticLaunchCompletion();
}

__global__ __launch_bounds__(512) void pass2_kernel(float* __restrict__ out) {
    const int t = threadIdx.x;       // 0..511 — one column each

    // Overlappable preamble is trivial; wait for pass1's trigger.
    cudaGridDependencySynchronize();

    // Column col: partial float index = rc*512 + col (coalesced, L2-resident).
    float s = 0.f;
    #pragma unroll
    for (int r = 0; r < N_CHUNKS; r++)
        s += g_colpart[r * N_COLS + t];
    double dnrm = (double)s * (double)s;
    double ds2  = (t < GRID1) ? (double)g_s2part[t] : 0.0;

    __shared__ double w_nrm[16];
    __shared__ double w_s2d[16];
    #pragma unroll
    for (int off = 16; off > 0; off >>= 1) {
        dnrm += __shfl_down_sync(0xFFFFFFFFu, dnrm, off);
        ds2  += __shfl_down_sync(0xFFFFFFFFu, ds2, off);
    }
    if ((t & 31) == 0) { w_nrm[t >> 5] = dnrm; w_s2d[t >> 5] = ds2; }
    __syncthreads();

    if (t == 0) {
        double NS = 0.0, S2 = 0.0;
        #pragma unroll
        for (int k = 0; k < 16; k++) { NS += w_nrm[k]; S2 += w_s2d[k]; }
        const double N = (double)N_ROWS;
        const double C = (double)N_COLS;
        double total = (2.0 * N * S2 - 2.0 * NS) / C;
        out[0] = (float)(total / (N * (N - 1.0)));
    }
}

extern "C" void kernel_launch(void* const* d_in, const int* in_sizes, int n_in,
                              void* d_out, int out_size) {
    const float* A = (const float*)d_in[0];
    float* out = (float*)d_out;
    (void)in_sizes; (void)n_in; (void)out_size;

    pass1_kernel<<<GRID1, BLK>>>(A);

    // pass2 with programmatic dependent launch: starts while pass1 runs,
    // blocks in cudaGridDependencySynchronize() until pass1 triggers.
    cudaLaunchConfig_t cfg = {};
    cfg.gridDim = dim3(1, 1, 1);
    cfg.blockDim = dim3(512, 1, 1);
    cfg.dynamicSmemBytes = 0;
    cfg.stream = 0;   // same (default) stream as pass1 — capture-consistent
    cudaLaunchAttribute attrs[1];
    attrs[0].id = cudaLaunchAttributeProgrammaticStreamSerialization;
    attrs[0].val.programmaticStreamSerializationAllowed = 1;
    cfg.attrs = attrs;
    cfg.numAttrs = 1;
    cudaLaunchKernelEx(&cfg, pass2_kernel, out);
}

// round 9
// speedup vs baseline: 1.1245x; 1.0078x over previous
#include <cuda_runtime.h>

// SharedSharedLoss: mean off-diagonal pairwise squared L2 distance / C.
// Identity: sum_{i,j} ||a_i - a_j||^2 = 2N * S2 - 2 * ||colsum||^2
// Single fused kernel: 16 column-strips x 8 row-chunks = 128 blocks.
// Each block reduces its strip to 32 column partials + 1 s2 partial (16 KB total),
// and the last block to finish does the tiny final reduce (threadfence pattern).
// Best-measured configuration across R3-R8 (8.19 us); bench floor ~8.2 us.

#define N_ROWS 4096
#define N_COLS 512
#define N_COLS4 128                  // float4 groups per row
#define N_STRIPS 16                  // column strips of 32 cols (8 float4 groups)
#define N_CHUNKS 8                   // row chunks of 512 rows
#define GRID (N_STRIPS * N_CHUNKS)   // 128 blocks
#define BLK 256                      // 8 groups x 32 row-lanes
#define ROWS_PER_CHUNK (N_ROWS / N_CHUNKS)        // 512
#define ROWS_PER_THREAD (ROWS_PER_CHUNK / 32)     // 16 (fully unrolled MLP)

// Deterministic scratch (no float atomics anywhere).
__device__ float g_colpart[GRID * 32];   // [rc*16+cs][32 cols] = 16 KB
__device__ float g_s2part[GRID];
__device__ unsigned int g_count = 0;     // completion counter (reset by last block)

__global__ __launch_bounds__(BLK) void fused_kernel(const float* __restrict__ A,
                                                    float* __restrict__ out) {
    const int t  = threadIdx.x;
    const int g  = t & 7;            // float4 group within strip (0..7)
    const int r0 = t >> 3;           // row lane (0..31)
    const int b  = blockIdx.x;
    const int cs = b & (N_STRIPS - 1);   // column strip
    const int rc = b >> 4;               // row chunk

    const float4* __restrict__ A4 = reinterpret_cast<const float4*>(A);

    // ---- Streaming phase: 512 rows x 32 cols per block ----
    float4 c = make_float4(0.f, 0.f, 0.f, 0.f);
    float s2 = 0.f;

    const int base = (rc * ROWS_PER_CHUNK + r0) * N_COLS4 + cs * 8 + g;
    #pragma unroll
    for (int i = 0; i < ROWS_PER_THREAD; i++) {
        float4 v = A4[base + i * 32 * N_COLS4];
        c.x += v.x; c.y += v.y; c.z += v.z; c.w += v.w;
        s2 += v.x * v.x + v.y * v.y + v.z * v.z + v.w * v.w;
    }

    // ---- Block reduce: colsums over the 32 row-lanes ----
    __shared__ float4 sh[BLK];
    __shared__ float warp_s2[BLK / 32];
    sh[t] = c;

    #pragma unroll
    for (int off = 16; off > 0; off >>= 1)
        s2 += __shfl_down_sync(0xFFFFFFFFu, s2, off);
    if ((t & 31) == 0) warp_s2[t >> 5] = s2;
    __syncthreads();

    // Tree-reduce sh over the r0 dimension (index = g + 8*r0).
    #pragma unroll
    for (int off = 128; off >= 8; off >>= 1) {
        if (t < off) {
            float4 o = sh[t + off];
            float4 m = sh[t];
            sh[t] = make_float4(m.x + o.x, m.y + o.y, m.z + o.z, m.w + o.w);
        }
        __syncthreads();
    }

    if (t < 8)
        reinterpret_cast<float4*>(g_colpart)[b * 8 + t] = sh[t];
    if (t == 0) {
        float tot = 0.f;
        #pragma unroll
        for (int w = 0; w < BLK / 32; w++) tot += warp_s2[w];
        g_s2part[b] = tot;
    }

    // ---- Last-block-done final reduce ----
    __threadfence();
    __syncthreads();
    __shared__ bool isLast;
    if (t == 0) {
        unsigned int old = atomicAdd(&g_count, 1u);
        isLast = (old == GRID - 1);
    }
    __syncthreads();
    if (!isLast) return;

    // Column sums: thread t handles cols t and t+256.
    // g_colpart layout: [(rc*16+cs)*32 + localcol]; col = cs*32+lc -> float index
    // rc*512 + col. Coalesced across threads.
    double dnrm = 0.0;
    #pragma unroll
    for (int k = 0; k < 2; k++) {
        const int col = t + k * 256;
        float s = 0.f;
        #pragma unroll
        for (int r = 0; r < N_CHUNKS; r++)
            s += g_colpart[r * N_COLS + col];
        dnrm += (double)s * (double)s;
    }
    double ds2 = (t < GRID) ? (double)g_s2part[t] : 0.0;

    // Reduce 256 doubles (8 warps) via shuffles + shared.
    __shared__ double w_nrm[BLK / 32];
    __shared__ double w_s2d[BLK / 32];
    #pragma unroll
    for (int off = 16; off > 0; off >>= 1) {
        dnrm += __shfl_down_sync(0xFFFFFFFFu, dnrm, off);
        ds2  += __shfl_down_sync(0xFFFFFFFFu, ds2, off);
    }
    if ((t & 31) == 0) { w_nrm[t >> 5] = dnrm; w_s2d[t >> 5] = ds2; }
    __syncthreads();

    if (t == 0) {
        double NS = 0.0, S2 = 0.0;
        #pragma unroll
        for (int w = 0; w < BLK / 32; w++) { NS += w_nrm[w]; S2 += w_s2d[w]; }
        const double N = (double)N_ROWS;
        const double C = (double)N_COLS;
        double total = (2.0 * N * S2 - 2.0 * NS) / C;
        out[0] = (float)(total / (N * (N - 1.0)));
        g_count = 0;   // reset for next graph replay
    }
}

extern "C" void kernel_launch(void* const* d_in, const int* in_sizes, int n_in,
                              void* d_out, int out_size) {
    const float* A = (const float*)d_in[0];
    float* out = (float*)d_out;
    (void)in_sizes; (void)n_in; (void)out_size;

    fused_kernel<<<GRID, BLK>>>(A, out);
}